// round 13
// baseline (speedup 1.0000x reference)
#include <cuda_runtime.h>
#include <math.h>

#define NBK  5
#define HD   32
#define DIN  4
#define TT   25
#define HIDD 64
#define TPB  128          // 4 warps
#define COLS 16           // sample columns per CTA
#define SPT  4            // samples per thread (float4-packed)
#define SPC  64           // samples per CTA
#define TILES 512         // 32768 / 64
#define GRID (TILES*NBK)  // 2560
#define JL   4            // j rows per lane (each half-warp owns 4 j)

typedef unsigned long long u64;

// Half-warp column split: lanes 0-15 and 16-31 of a warp process the SAME 16
// sample columns but DIFFERENT 4-row j groups -> per-warp weight-LDS shape is
// unchanged (2 uniform addresses = 1 wavefront) while state-LDS bytes halve
// (upper half broadcasts the lower half's addresses). 64 samples/CTA shrinks
// smem to 75 KB -> 3 CTAs/SM = 12 warps with ALL weights in smem.
// c-state in thread-private global scratch (R12: proven free).
struct SmemLayout {
    float Wp0p[DIN][HD][4];   //  2048 B  (i,f,o rows prescaled by 0.5)
    float Wh0p[HD][HD][4];    // 16384 B
    float Wp1p[HD][HD][4];    // 16384 B
    float Wh1p[HD][HD][4];    // 16384 B
    float bp0[HD][4];         //   512 B
    float bp1[HD][4];         //   512 B
    float4 h0s[2][HD][COLS];  // 16384 B (double-buffered)
    float4 h1s[HD][COLS];     //  8192 B
};                            // 76800 B -> 3 CTAs/SM (12 warps)

// MLP overlay offsets (floats) into the weight region (reused after recurrence)
#define OV_W1 0
#define OV_B1 2048
#define OV_W2 2112
#define OV_B2 6208

// c-state scratch: thread-private addresses, same-thread read/write only.
__device__ float4 g_c[GRID][2][HD][COLS];

__device__ __forceinline__ u64 pk2(float v) {
    u64 r; asm("mov.b64 %0, {%1, %1};" : "=l"(r) : "f"(v)); return r;
}
__device__ __forceinline__ u64 f2fma(u64 a, u64 b, u64 c) {
    u64 d; asm("fma.rn.f32x2 %0, %1, %2, %3;" : "=l"(d) : "l"(a), "l"(b), "l"(c));
    return d;
}
__device__ __forceinline__ void unpk(u64 v, float& lo, float& hi) {
    asm("mov.b64 {%0, %1}, %2;" : "=f"(lo), "=f"(hi) : "l"(v));
}
__device__ __forceinline__ float tanhfast(float x) {
    float y; asm("tanh.approx.f32 %0, %1;" : "=f"(y) : "f"(x)); return y;
}
// sigmoid of a PRESCALED (x/2) preactivation
__device__ __forceinline__ float sigp(float v) {
    return fmaf(0.5f, tanhfast(v), 0.5f);
}

__global__ void __launch_bounds__(TPB, 3) lstm_fused(
    const float* __restrict__ x,    const float* __restrict__ mask,
    const float* __restrict__ Wih0, const float* __restrict__ Whh0,
    const float* __restrict__ bih0, const float* __restrict__ bhh0,
    const float* __restrict__ Wih1, const float* __restrict__ Whh1,
    const float* __restrict__ bih1, const float* __restrict__ bhh1,
    const float* __restrict__ W1,   const float* __restrict__ b1,
    const float* __restrict__ W2,   const float* __restrict__ b2,
    float* __restrict__ out)
{
    extern __shared__ float smraw[];
    SmemLayout* S = reinterpret_cast<SmemLayout*>(smraw);
    const int tid   = threadIdx.x;
    const int col   = tid & 15;                         // sample column
    const int jbase = ((tid >> 5) << 3) + (((tid >> 4) & 1) << 2);  // half-warp j group
    const int ib    = 4 - (blockIdx.x >> 9);            // heavy blocks first
    const int tile  = blockIdx.x & (TILES - 1);

    float4* gc0 = &g_c[blockIdx.x][0][0][0];
    float4* gc1 = &g_c[blockIdx.x][1][0][0];

    // ---- stage weights into SMEM (interleaved, i/f/o rows prescaled by 0.5) ----
    {
        const float* wih0 = Wih0 + ib * 4 * HD * DIN;
        for (int idx = tid; idx < 4 * HD * DIN; idx += TPB) {
            int r = idx / DIN, k = idx % DIN, g = r >> 5, j = r & 31;
            float s = (g == 2) ? 1.0f : 0.5f;
            S->Wp0p[k][j][g] = s * wih0[idx];
        }
        const float* whh0 = Whh0 + ib * 4 * HD * HD;
        const float* wih1 = Wih1 + ib * 4 * HD * HD;
        const float* whh1 = Whh1 + ib * 4 * HD * HD;
        for (int idx = tid; idx < 4 * HD * HD; idx += TPB) {
            int r = idx / HD, k = idx % HD, g = r >> 5, j = r & 31;
            float s = (g == 2) ? 1.0f : 0.5f;
            S->Wh0p[k][j][g] = s * whh0[idx];
            S->Wp1p[k][j][g] = s * wih1[idx];
            S->Wh1p[k][j][g] = s * whh1[idx];
        }
        for (int idx = tid; idx < 4 * HD; idx += TPB) {
            int g = idx >> 5, j = idx & 31;
            float s = (g == 2) ? 1.0f : 0.5f;
            S->bp0[j][g] = s * (bih0[ib * 4 * HD + idx] + bhh0[ib * 4 * HD + idx]);
            S->bp1[j][g] = s * (bih1[ib * 4 * HD + idx] + bhh1[ib * 4 * HD + idx]);
        }
        // zero h0s[0] and h1s (h0s[1] is write-before-read)
        float4* st0 = reinterpret_cast<float4*>(&S->h0s[0][0][0]);
        for (int i = tid; i < HD * COLS; i += TPB) st0[i] = make_float4(0.f, 0.f, 0.f, 0.f);
        float4* st1 = reinterpret_cast<float4*>(&S->h1s[0][0]);
        for (int i = tid; i < HD * COLS; i += TPB) st1[i] = make_float4(0.f, 0.f, 0.f, 0.f);
    }
    __syncthreads();

    float hnr[JL][SPT];

    const int Ti = 5 * (ib + 1);
    // per-lane base pointers; per-step addresses computed on the fly
    const float4* xb = reinterpret_cast<const float4*>(x)    + (size_t)(tile * SPC + col) * TT + (TT - Ti);
    const float4* mb = reinterpret_cast<const float4*>(mask) + (size_t)(tile * SPC + col) * TT + (TT - Ti);

    for (int st = 0; st < Ti; st++) {
        const int rb = st & 1, wb = 1 - rb;     // h0 double-buffer parity
        float xmf[SPT][DIN];
#pragma unroll
        for (int s4 = 0; s4 < SPT; s4++) {
            float4 xv = __ldg(xb + (size_t)s4 * COLS * TT + st);
            float4 mv = __ldg(mb + (size_t)s4 * COLS * TT + st);
            xmf[s4][0] = xv.x * mv.x; xmf[s4][1] = xv.y * mv.y;
            xmf[s4][2] = xv.z * mv.z; xmf[s4][3] = xv.w * mv.w;
        }

        // ================= layer 0 (reads h0s[rb]) -- single pass =================
        {
            float4 cp[JL];
#pragma unroll
            for (int q = 0; q < JL; q++)
                cp[q] = (st == 0) ? make_float4(0.f, 0.f, 0.f, 0.f)
                                  : __ldg(&gc0[(jbase + q) * COLS + col]);

            u64 aI[SPT][JL], aG[SPT][JL];
#pragma unroll
            for (int q = 0; q < JL; q++) {
                ulonglong2 bb = *reinterpret_cast<const ulonglong2*>(S->bp0[jbase + q]);
#pragma unroll
                for (int s4 = 0; s4 < SPT; s4++) { aI[s4][q] = bb.x; aG[s4][q] = bb.y; }
            }
#pragma unroll
            for (int k = 0; k < DIN; k++) {
                u64 hx[SPT];
#pragma unroll
                for (int s4 = 0; s4 < SPT; s4++) hx[s4] = pk2(xmf[s4][k]);
#pragma unroll
                for (int q = 0; q < JL; q++) {
                    ulonglong2 w = *reinterpret_cast<const ulonglong2*>(S->Wp0p[k][jbase + q]);
#pragma unroll
                    for (int s4 = 0; s4 < SPT; s4++) {
                        aI[s4][q] = f2fma(w.x, hx[s4], aI[s4][q]);
                        aG[s4][q] = f2fma(w.y, hx[s4], aG[s4][q]);
                    }
                }
            }
#pragma unroll 8
            for (int k = 0; k < HD; k++) {
                float4 hv = S->h0s[rb][k][col];
                u64 hh[SPT];
                hh[0] = pk2(hv.x); hh[1] = pk2(hv.y); hh[2] = pk2(hv.z); hh[3] = pk2(hv.w);
#pragma unroll
                for (int q = 0; q < JL; q++) {
                    ulonglong2 w = *reinterpret_cast<const ulonglong2*>(S->Wh0p[k][jbase + q]);
#pragma unroll
                    for (int s4 = 0; s4 < SPT; s4++) {
                        aI[s4][q] = f2fma(w.x, hh[s4], aI[s4][q]);
                        aG[s4][q] = f2fma(w.y, hh[s4], aG[s4][q]);
                    }
                }
            }
#pragma unroll
            for (int q = 0; q < JL; q++) {
                float cc[SPT];
#pragma unroll
                for (int s4 = 0; s4 < SPT; s4++) {
                    float ai, af, ag, ao;
                    unpk(aI[s4][q], ai, af); unpk(aG[s4][q], ag, ao);
                    float cv = (s4 == 0) ? cp[q].x : (s4 == 1) ? cp[q].y
                             : (s4 == 2) ? cp[q].z : cp[q].w;
                    cc[s4] = sigp(af) * cv + sigp(ai) * tanhfast(ag);
                    hnr[q][s4] = sigp(ao) * tanhfast(cc[s4]);
                }
                gc0[(jbase + q) * COLS + col] = make_float4(cc[0], cc[1], cc[2], cc[3]);
            }
        }
#pragma unroll
        for (int q = 0; q < JL; q++)
            S->h0s[wb][jbase + q][col] = make_float4(hnr[q][0], hnr[q][1], hnr[q][2], hnr[q][3]);
        __syncthreads();   // new h0 visible; also orders prev-step h1 writes

        // ========== layer 1 (reads h0s[wb] new + h1s old) -- single pass ==========
        {
            float4 cp[JL];
#pragma unroll
            for (int q = 0; q < JL; q++)
                cp[q] = (st == 0) ? make_float4(0.f, 0.f, 0.f, 0.f)
                                  : __ldg(&gc1[(jbase + q) * COLS + col]);

            u64 aI[SPT][JL], aG[SPT][JL];
#pragma unroll
            for (int q = 0; q < JL; q++) {
                ulonglong2 bb = *reinterpret_cast<const ulonglong2*>(S->bp1[jbase + q]);
#pragma unroll
                for (int s4 = 0; s4 < SPT; s4++) { aI[s4][q] = bb.x; aG[s4][q] = bb.y; }
            }
#pragma unroll 8
            for (int k = 0; k < HD; k++) {
                float4 hv = S->h0s[wb][k][col];
                u64 hh[SPT];
                hh[0] = pk2(hv.x); hh[1] = pk2(hv.y); hh[2] = pk2(hv.z); hh[3] = pk2(hv.w);
#pragma unroll
                for (int q = 0; q < JL; q++) {
                    ulonglong2 w = *reinterpret_cast<const ulonglong2*>(S->Wp1p[k][jbase + q]);
#pragma unroll
                    for (int s4 = 0; s4 < SPT; s4++) {
                        aI[s4][q] = f2fma(w.x, hh[s4], aI[s4][q]);
                        aG[s4][q] = f2fma(w.y, hh[s4], aG[s4][q]);
                    }
                }
            }
#pragma unroll 8
            for (int k = 0; k < HD; k++) {
                float4 hv = S->h1s[k][col];
                u64 hh[SPT];
                hh[0] = pk2(hv.x); hh[1] = pk2(hv.y); hh[2] = pk2(hv.z); hh[3] = pk2(hv.w);
#pragma unroll
                for (int q = 0; q < JL; q++) {
                    ulonglong2 w = *reinterpret_cast<const ulonglong2*>(S->Wh1p[k][jbase + q]);
#pragma unroll
                    for (int s4 = 0; s4 < SPT; s4++) {
                        aI[s4][q] = f2fma(w.x, hh[s4], aI[s4][q]);
                        aG[s4][q] = f2fma(w.y, hh[s4], aG[s4][q]);
                    }
                }
            }
            __syncthreads();   // all layer-1 reads of old h1s complete
#pragma unroll
            for (int q = 0; q < JL; q++) {
                float cc[SPT];
#pragma unroll
                for (int s4 = 0; s4 < SPT; s4++) {
                    float ai, af, ag, ao;
                    unpk(aI[s4][q], ai, af); unpk(aG[s4][q], ag, ao);
                    float cv = (s4 == 0) ? cp[q].x : (s4 == 1) ? cp[q].y
                             : (s4 == 2) ? cp[q].z : cp[q].w;
                    cc[s4] = sigp(af) * cv + sigp(ai) * tanhfast(ag);
                    hnr[q][s4] = sigp(ao) * tanhfast(cc[s4]);
                }
                gc1[(jbase + q) * COLS + col] = make_float4(cc[0], cc[1], cc[2], cc[3]);
                S->h1s[jbase + q][col] = make_float4(hnr[q][0], hnr[q][1], hnr[q][2], hnr[q][3]);
            }
        }
        // h1 writes ordered for next step's reads by the first barrier of next step
    }

    // ---- MLP head: 2 threads per sample (64 samples, 128 threads) ----
    __syncthreads();   // h1s final visible; weight region about to be reused
    float* ov = smraw;
    for (int idx = tid; idx < HIDD * HD; idx += TPB)   ov[OV_W1 + idx] = W1[idx];
    for (int idx = tid; idx < HIDD * HIDD; idx += TPB) {
        int n = idx / HIDD, m = idx % HIDD;
        ov[OV_W2 + m * HIDD + n] = W2[idx];            // transposed [m][n]
    }
    if (tid < HIDD) { ov[OV_B1 + tid] = b1[tid]; ov[OV_B2 + tid] = b2[tid]; }
    __syncthreads();

    const int sidx = tid & 63;       // sample within CTA
    const int half = tid >> 6;       // which 32 outputs
    const int scol = sidx & 15;
    const int sq   = sidx >> 4;      // float4 component

    float hr[HD];
#pragma unroll
    for (int k = 0; k < HD; k++) {
        float4 v = S->h1s[k][scol];
        hr[k] = (sq == 0) ? v.x : (sq == 1) ? v.y : (sq == 2) ? v.z : v.w;
    }

    float acc2[HIDD / 2];
#pragma unroll
    for (int n = 0; n < HIDD / 2; n++) acc2[n] = ov[OV_B2 + half * (HIDD / 2) + n];

    for (int m = 0; m < HIDD; m++) {
        float tm = ov[OV_B1 + m];
        const float4* w1r = reinterpret_cast<const float4*>(&ov[OV_W1 + m * HD]);
#pragma unroll
        for (int q = 0; q < HD / 4; q++) {
            float4 w = w1r[q];
            tm += hr[4 * q + 0] * w.x + hr[4 * q + 1] * w.y
                + hr[4 * q + 2] * w.z + hr[4 * q + 3] * w.w;
        }
        tm = 0.5f * tm * (1.0f + erff(tm * 0.70710678118654752f));   // exact gelu
        const float4* w2r = reinterpret_cast<const float4*>(
            &ov[OV_W2 + m * HIDD + half * (HIDD / 2)]);
#pragma unroll
        for (int q = 0; q < HIDD / 8; q++) {
            float4 w = w2r[q];
            acc2[4 * q + 0] += tm * w.x; acc2[4 * q + 1] += tm * w.y;
            acc2[4 * q + 2] += tm * w.z; acc2[4 * q + 3] += tm * w.w;
        }
    }

    const int bS = tile * SPC + sq * COLS + scol;
    float4* op = reinterpret_cast<float4*>(
        out + ((size_t)bS * NBK + ib) * HIDD + half * (HIDD / 2));
#pragma unroll
    for (int q = 0; q < HIDD / 8; q++)
        op[q] = make_float4(acc2[4 * q], acc2[4 * q + 1],
                            acc2[4 * q + 2], acc2[4 * q + 3]);
}

extern "C" void kernel_launch(void* const* d_in, const int* in_sizes, int n_in,
                              void* d_out, int out_size)
{
    const float* x    = (const float*)d_in[0];
    const float* mask = (const float*)d_in[1];
    const float* Wih0 = (const float*)d_in[2];
    const float* Whh0 = (const float*)d_in[3];
    const float* bih0 = (const float*)d_in[4];
    const float* bhh0 = (const float*)d_in[5];
    const float* Wih1 = (const float*)d_in[6];
    const float* Whh1 = (const float*)d_in[7];
    const float* bih1 = (const float*)d_in[8];
    const float* bhh1 = (const float*)d_in[9];
    const float* W1   = (const float*)d_in[10];
    const float* b1   = (const float*)d_in[11];
    const float* W2   = (const float*)d_in[12];
    const float* b2   = (const float*)d_in[13];
    float* out = (float*)d_out;

    const size_t smem = sizeof(SmemLayout);   // 76800 B -> 3 CTAs/SM
    cudaFuncSetAttribute(lstm_fused, cudaFuncAttributeMaxDynamicSharedMemorySize,
                         (int)smem);
    lstm_fused<<<GRID, TPB, smem>>>(x, mask, Wih0, Whh0, bih0, bhh0,
                                    Wih1, Whh1, bih1, bhh1, W1, b1, W2, b2, out);
}